// round 5
// baseline (speedup 1.0000x reference)
#include <cuda_runtime.h>
#include <stdint.h>

// out[i] = in[i] + 0.1*sqrt(2)*erfinv(u(i)), matching
// jax.random.normal(jax.random.key(42), (64,3,512,512), f32),
// jax_threefry_partitionable=True:
//   (y0,y1)=threefry2x32((0,42),(0,i)); bits=y0^y1
//   u = clamp(bitcast((bits>>9)|0x40000000)-3.0f, LO),  LO=-0.99999994
//   noise = 0.1*sqrt(2)*erfinv(u)  [Giles; central poly truncated to deg 4,
//                                   scale folded into coefficients]
// Perf structure: issue-bound. x0-lane adds on FMA pipe (mad.lo with opaque
// 'one'); the three r=13 rounds use IMAD.WIDE (x*2^13 -> {lo,hi}) + one fused
// 3-input LOP3 ((lo|hi)^x0), rebalancing alu vs fma to ~41/41 per element.

__device__ __forceinline__ uint32_t mad1(uint32_t a, uint32_t b, uint32_t c) {
    uint32_t d;
    asm("mad.lo.u32 %0, %1, %2, %3;" : "=r"(d) : "r"(a), "r"(b), "r"(c));
    return d;
}

// rotl(x,13)^x0 via widening multiply (m = 2^13, opaque):
// IMAD.WIDE (fma pipe) + single LOP3 (lo|hi)^x0 (alu pipe).
__device__ __forceinline__ uint32_t rot13x(uint32_t x, uint32_t m, uint32_t x0) {
    unsigned long long p;
    asm("mul.wide.u32 %0, %1, %2;" : "=l"(p) : "r"(x), "r"(m));
    return (((uint32_t)p) | ((uint32_t)(p >> 32))) ^ x0;
}

struct TFK {
    uint32_t one, m13, k1, k2, k2p1, c2, k1p3, k2p4, c5;
};

// 20-round threefry2x32 on (0, ctr); returns x0^x1.
__device__ __forceinline__ uint32_t tf_bits(uint32_t ctr, const TFK& K) {
#define TF_RND(r) { x0 = mad1(x1, K.one, x0); \
                    x1 = __funnelshift_l(x1, x1, (r)) ^ x0; }
    uint32_t x1 = mad1(K.one, K.k1, ctr);  // x1 = ctr + 42 (key inj 0)
    uint32_t x0 = x1;                      // round 1: x0 = 0 + x1
    x1 = rot13x(x1, K.m13, x0);
    TF_RND(15) TF_RND(26) TF_RND(6)
    x0 = mad1(K.one, K.k1, x0);  x1 = mad1(K.one, K.k2p1, x1);
    TF_RND(17) TF_RND(29) TF_RND(16) TF_RND(24)
    x0 = mad1(K.one, K.k2, x0);  x1 = mad1(K.one, K.c2, x1);
    x0 = mad1(x1, K.one, x0);    x1 = rot13x(x1, K.m13, x0);
    TF_RND(15) TF_RND(26) TF_RND(6)
    /* x0 += k0 = 0 */           x1 = mad1(K.one, K.k1p3, x1);
    TF_RND(17) TF_RND(29) TF_RND(16) TF_RND(24)
    x0 = mad1(K.one, K.k1, x0);  x1 = mad1(K.one, K.k2p4, x1);
    x0 = mad1(x1, K.one, x0);    x1 = rot13x(x1, K.m13, x0);
    TF_RND(15) TF_RND(26) TF_RND(6)
    x0 = mad1(K.one, K.k2, x0);  x1 = mad1(K.one, K.c5, x1);
#undef TF_RND
    return x0 ^ x1;
}

// Rare tail branch (w >= 5 i.e. t >= 2.5): Giles tail poly, scale folded.
__device__ __forceinline__ float noise_tail_f(float t, float u) {
    float w = t + 2.5f;
    float s = sqrtf(w) - 3.0f;
    float p =       -2.83145467e-05f;
    p = fmaf(p, s,   1.42766481e-05f);
    p = fmaf(p, s,   1.90824894e-04f);
    p = fmaf(p, s,  -5.19499916e-04f);
    p = fmaf(p, s,   8.11690563e-04f);
    p = fmaf(p, s,  -1.07798485e-03f);
    p = fmaf(p, s,   1.33486521e-03f);
    p = fmaf(p, s,   1.41657794e-01f);
    p = fmaf(p, s,   4.00644237e-01f);
    return p * u;
}

__global__ void __launch_bounds__(256)
noise_kernel(const float4* __restrict__ in, float4* __restrict__ out,
             int n8, uint32_t one, uint32_t m13) {
    int tid = blockIdx.x * blockDim.x + threadIdx.x;
    if (tid >= n8) return;

    TFK K;
    K.one = one; K.m13 = m13;
    K.k1 = 42u * one;
    K.k2 = 0x1BD11BF0u * one;   // 0x1BD11BDA ^ 0 ^ 42
    K.k2p1 = K.k2 + 1u;  K.c2 = 2u * one;
    K.k1p3 = K.k1 + 3u;  K.k2p4 = K.k2 + 4u;  K.c5 = 5u * one;

    float4 a0 = in[2 * tid];
    float4 a1 = in[2 * tid + 1];
    uint32_t c = 8u * (uint32_t)tid;

    float u[8], lt[8], nz[8];
#pragma unroll
    for (int j = 0; j < 8; j++) {
        uint32_t y  = tf_bits(c + (uint32_t)j, K);
        uint32_t vb = mad1(K.one, 0x40000000u, y >> 9);   // 2*[1,2) in [2,4)
        float uu = __uint_as_float(vb) - 3.0f;            // exact (Sterbenz)
        uu = fmaxf(uu, -0.99999994f);                     // ref clamp at LO
        float g = fmaf(-uu, uu, 1.0f);                    // 1 - u^2 > 0
        float lg;
        asm("lg2.approx.f32 %0, %1;" : "=f"(lg) : "f"(g));
        float t = fmaf(lg, -0.693147181f, -2.5f);         // w - 2.5
        // Central Giles poly, truncated to degree 4, 0.1*sqrt(2) folded in.
        float p =        3.09122925e-05f;
        p = fmaf(p, t,  -1.77302644e-04f);
        p = fmaf(p, t,  -5.90813690e-04f);
        p = fmaf(p, t,   3.48802861e-02f);
        p = fmaf(p, t,   2.12331951e-01f);
        u[j] = uu; lt[j] = t; nz[j] = p * uu;
    }

    // One branch per thread for the rare tail (|u| > 0.99663).
    float m01 = fmaxf(lt[0], lt[1]), m23 = fmaxf(lt[2], lt[3]);
    float m45 = fmaxf(lt[4], lt[5]), m67 = fmaxf(lt[6], lt[7]);
    float mx = fmaxf(fmaxf(m01, m23), fmaxf(m45, m67));
    if (mx >= 2.5f) {
#pragma unroll
        for (int j = 0; j < 8; j++)
            if (lt[j] >= 2.5f) nz[j] = noise_tail_f(lt[j], u[j]);
    }

    float4 r0, r1;
    r0.x = a0.x + nz[0];  r0.y = a0.y + nz[1];
    r0.z = a0.z + nz[2];  r0.w = a0.w + nz[3];
    r1.x = a1.x + nz[4];  r1.y = a1.y + nz[5];
    r1.z = a1.z + nz[6];  r1.w = a1.w + nz[7];
    out[2 * tid]     = r0;
    out[2 * tid + 1] = r1;
}

// Scalar fallback for n % 8 != 0 (not hit for this shape).
__global__ void noise_scalar_kernel(const float* __restrict__ in,
                                    float* __restrict__ out,
                                    unsigned int start, unsigned int n,
                                    uint32_t one, uint32_t m13) {
    unsigned int i = start + blockIdx.x * blockDim.x + threadIdx.x;
    if (i >= n) return;
    TFK K;
    K.one = one; K.m13 = m13;
    K.k1 = 42u * one; K.k2 = 0x1BD11BF0u * one;
    K.k2p1 = K.k2 + 1u; K.c2 = 2u * one;
    K.k1p3 = K.k1 + 3u; K.k2p4 = K.k2 + 4u; K.c5 = 5u * one;
    uint32_t y  = tf_bits(i, K);
    uint32_t vb = mad1(one, 0x40000000u, y >> 9);
    float u = fmaxf(__uint_as_float(vb) - 3.0f, -0.99999994f);
    float g = fmaf(-u, u, 1.0f);
    float lg;
    asm("lg2.approx.f32 %0, %1;" : "=f"(lg) : "f"(g));
    float t = fmaf(lg, -0.693147181f, -2.5f);
    float p =        3.09122925e-05f;
    p = fmaf(p, t,  -1.77302644e-04f);
    p = fmaf(p, t,  -5.90813690e-04f);
    p = fmaf(p, t,   3.48802861e-02f);
    p = fmaf(p, t,   2.12331951e-01f);
    float nz = (t < 2.5f) ? p * u : noise_tail_f(t, u);
    out[i] = in[i] + nz;
}

extern "C" void kernel_launch(void* const* d_in, const int* in_sizes, int n_in,
                              void* d_out, int out_size) {
    const float* in = (const float*)d_in[0];
    float* out = (float*)d_out;

    unsigned int n = (unsigned int)in_sizes[0];  // 50331648
    int n8 = (int)(n / 8u);                      // 6291456

    if (n8 > 0) {
        int threads = 256;
        int blocks = (n8 + threads - 1) / threads;  // 24576
        noise_kernel<<<blocks, threads>>>((const float4*)in, (float4*)out,
                                          n8, 1u, 1u << 13);
    }
    unsigned int done = (unsigned int)n8 * 8u;
    if (done < n) {
        unsigned int rem = n - done;
        noise_scalar_kernel<<<(rem + 255) / 256, 256>>>(in, out, done, n,
                                                        1u, 1u << 13);
    }
}

// round 6
// speedup vs baseline: 1.0388x; 1.0388x over previous
#include <cuda_runtime.h>
#include <stdint.h>

// out[i] = in[i] + 0.1*sqrt(2)*erfinv(u(i)), matching
// jax.random.normal(jax.random.key(42), (64,3,512,512), f32),
// jax_threefry_partitionable=True:
//   (y0,y1) = threefry2x32((0,42),(0,i));  bits = y0 ^ y1
//   f = bitcast((bits>>9)|0x3F800000) - 1;  u = fma(f, 2, LO), LO=-0.99999994
//   noise = 0.1*sqrt(2)*erfinv(u)   [Giles; central poly deg 4, scale folded]
//
// Issue-slot-bound kernel (~91 instr/elem). x0-lane adds + key injections on
// the FMA pipe via mad.lo.u32 with an opaque 'one'; round 1 eliminated
// algebraically (x0 == 0); log fused as fma(lg2(g), -ln2, -2.5).

__device__ __forceinline__ uint32_t mad1(uint32_t a, uint32_t b, uint32_t c) {
    uint32_t d;
    asm("mad.lo.u32 %0, %1, %2, %3;" : "=r"(d) : "r"(a), "r"(b), "r"(c));
    return d;
}

struct TFK {
    uint32_t one, k1, k2, k2p1, c2, k1p3, k2p4, c5;
};

// 20-round threefry2x32 on (0, ctr); returns x0^x1.
// Round 1 uses x0==0: x0 <- x1, x1 <- rotl(x1,13)^x1.
__device__ __forceinline__ uint32_t tf_bits(uint32_t ctr, const TFK& K) {
#define TF_RND(r) { x0 = mad1(x1, K.one, x0); \
                    x1 = __funnelshift_l(x1, x1, (r)) ^ x0; }
    uint32_t x0 = ctr + 42u;                         // = x1 after round-1 add
    uint32_t x1 = __funnelshift_l(x0, x0, 13) ^ x0;  // round 1
    TF_RND(15) TF_RND(26) TF_RND(6)
    x0 = mad1(K.one, K.k1, x0);  x1 = mad1(K.one, K.k2p1, x1);
    TF_RND(17) TF_RND(29) TF_RND(16) TF_RND(24)
    x0 = mad1(K.one, K.k2, x0);  x1 = mad1(K.one, K.c2, x1);
    TF_RND(13) TF_RND(15) TF_RND(26) TF_RND(6)
    /* x0 += k0 = 0 */           x1 = mad1(K.one, K.k1p3, x1);
    TF_RND(17) TF_RND(29) TF_RND(16) TF_RND(24)
    x0 = mad1(K.one, K.k1, x0);  x1 = mad1(K.one, K.k2p4, x1);
    TF_RND(13) TF_RND(15) TF_RND(26) TF_RND(6)
    x0 = mad1(K.one, K.k2, x0);  x1 = mad1(K.one, K.c5, x1);
#undef TF_RND
    return x0 ^ x1;
}

// bits -> u in [LO, 1), LO = nextafter(-1,0); bit-exact vs reference, no
// clamp needed (f >= 0 ==> u >= LO).
__device__ __forceinline__ float bits_to_u(uint32_t b) {
    float f = __uint_as_float((b >> 9) | 0x3F800000u) - 1.0f;
    return fmaf(f, 2.0f, -0.99999994f);
}

// Rare tail (t = w-2.5 >= 2.5, i.e. |u| > 0.99663): full Giles tail poly,
// 0.1*sqrt(2) folded into coefficients.
__device__ __forceinline__ float noise_tail_f(float t, float u) {
    float s = sqrtf(t + 2.5f) - 3.0f;
    float p =       -2.83145467e-05f;
    p = fmaf(p, s,   1.42766481e-05f);
    p = fmaf(p, s,   1.90824894e-04f);
    p = fmaf(p, s,  -5.19499916e-04f);
    p = fmaf(p, s,   8.11690563e-04f);
    p = fmaf(p, s,  -1.07798485e-03f);
    p = fmaf(p, s,   1.33486521e-03f);
    p = fmaf(p, s,   1.41657794e-01f);
    p = fmaf(p, s,   4.00644237e-01f);
    return p * u;
}

__global__ void __launch_bounds__(256)
noise_vec_kernel(const float4* __restrict__ in, float4* __restrict__ out,
                 int n4, uint32_t one) {
    int tid = blockIdx.x * blockDim.x + threadIdx.x;
    if (tid >= n4) return;

    TFK K;
    K.one = one;
    K.k1 = 42u * one;
    K.k2 = 0x1BD11BF0u * one;     // 0x1BD11BDA ^ 0 ^ 42
    K.k2p1 = K.k2 + 1u;  K.c2 = 2u * one;
    K.k1p3 = K.k1 + 3u;  K.k2p4 = K.k2 + 4u;  K.c5 = 5u * one;

    float4 a = in[tid];
    uint32_t c = 4u * (uint32_t)tid;

    float u[4], t[4], nz[4];
#pragma unroll
    for (int j = 0; j < 4; j++) {
        uint32_t y = tf_bits(c + (uint32_t)j, K);
        float uu = bits_to_u(y);
        float g = fmaf(-uu, uu, 1.0f);                // 1 - u^2, in (0, 1]
        float lg;
        asm("lg2.approx.f32 %0, %1;" : "=f"(lg) : "f"(g));
        float tt = fmaf(lg, -0.693147181f, -2.5f);    // w - 2.5
        // Central Giles poly deg 4, 0.1*sqrt(2) folded in.
        float p =        3.09122925e-05f;
        p = fmaf(p, tt, -1.77302644e-04f);
        p = fmaf(p, tt, -5.90813690e-04f);
        p = fmaf(p, tt,  3.48802861e-02f);
        p = fmaf(p, tt,  2.12331951e-01f);
        u[j] = uu; t[j] = tt; nz[j] = p * uu;
    }

    // One branch per thread for the rare tail (|u| > 0.99663).
    float mx = fmaxf(fmaxf(t[0], t[1]), fmaxf(t[2], t[3]));
    if (mx >= 2.5f) {
#pragma unroll
        for (int j = 0; j < 4; j++)
            if (t[j] >= 2.5f) nz[j] = noise_tail_f(t[j], u[j]);
    }

    float4 r;
    r.x = a.x + nz[0];
    r.y = a.y + nz[1];
    r.z = a.z + nz[2];
    r.w = a.w + nz[3];
    out[tid] = r;
}

// Scalar fallback for n % 4 != 0 (not hit for this shape).
__global__ void noise_scalar_kernel(const float* __restrict__ in,
                                    float* __restrict__ out,
                                    unsigned int start, unsigned int n,
                                    uint32_t one) {
    unsigned int i = start + blockIdx.x * blockDim.x + threadIdx.x;
    if (i >= n) return;
    TFK K;
    K.one = one;
    K.k1 = 42u * one; K.k2 = 0x1BD11BF0u * one;
    K.k2p1 = K.k2 + 1u; K.c2 = 2u * one;
    K.k1p3 = K.k1 + 3u; K.k2p4 = K.k2 + 4u; K.c5 = 5u * one;
    uint32_t y = tf_bits(i, K);
    float u = bits_to_u(y);
    float g = fmaf(-u, u, 1.0f);
    float lg;
    asm("lg2.approx.f32 %0, %1;" : "=f"(lg) : "f"(g));
    float t = fmaf(lg, -0.693147181f, -2.5f);
    float p =        3.09122925e-05f;
    p = fmaf(p, t,  -1.77302644e-04f);
    p = fmaf(p, t,  -5.90813690e-04f);
    p = fmaf(p, t,   3.48802861e-02f);
    p = fmaf(p, t,   2.12331951e-01f);
    float nz = (t < 2.5f) ? p * u : noise_tail_f(t, u);
    out[i] = in[i] + nz;
}

extern "C" void kernel_launch(void* const* d_in, const int* in_sizes, int n_in,
                              void* d_out, int out_size) {
    const float* in = (const float*)d_in[0];
    float* out = (float*)d_out;

    unsigned int n = (unsigned int)in_sizes[0];  // 50331648
    int n4 = (int)(n / 4u);                      // 12582912

    if (n4 > 0) {
        int threads = 256;
        int blocks = (n4 + threads - 1) / threads;  // 49152
        noise_vec_kernel<<<blocks, threads>>>((const float4*)in, (float4*)out,
                                              n4, 1u);
    }
    unsigned int done = (unsigned int)n4 * 4u;
    if (done < n) {
        unsigned int rem = n - done;
        noise_scalar_kernel<<<(rem + 255) / 256, 256>>>(in, out, done, n, 1u);
    }
}

// round 7
// speedup vs baseline: 1.0956x; 1.0546x over previous
#include <cuda_runtime.h>
#include <stdint.h>

// out[i] = in[i] + 0.1*sqrt(2)*erfinv(u(i)), matching
// jax.random.normal(jax.random.key(42), (64,3,512,512), f32),
// jax_threefry_partitionable=True:
//   (y0,y1) = threefry2x32((0,42),(0,i));  bits = y0 ^ y1
//   f = bitcast((bits>>9)|0x3F800000) - 1;  u = fma(f, 2, LO), LO=-0.99999994
//   noise = 0.1*sqrt(2)*erfinv(u)   [Giles; central poly deg 4, scale folded]
//
// Issue/alu-bound. Cuts this round: IADD3 3-input fusion of key injections
// (k as immediate), single-SHF bits->float via funnelshift_r(y, 0x7F, 9),
// plain adds so ptxas alternates IMAD/IADD3 across pipes itself.

// 20-round threefry2x32 on (0, ctr), v = ctr + 42 (key-injection 0 applied).
// Returns x0 ^ x1 after the final injection.
__device__ __forceinline__ uint32_t tf_bits(uint32_t v) {
    // round 1 (x0 starts at 0): x0 = v; x1 = rotl(v,13)^v
    uint32_t x0 = v;
    uint32_t x1 = __funnelshift_l(v, v, 13) ^ v;
    // rounds 2-4
    x0 += x1; x1 = __funnelshift_l(x1, x1, 15) ^ x0;
    x0 += x1; x1 = __funnelshift_l(x1, x1, 26) ^ x0;
    x0 += x1; x1 = __funnelshift_l(x1, x1,  6) ^ x0;
    // inj1 (x0+=42, x1+=k2+1) merged into round 5's x0-add
    x1 += 0x1BD11BF1u;                      // k2 + 1
    x0 = x0 + 42u + x1;                     // IADD3(x0, 42, x1)
    x1 = __funnelshift_l(x1, x1, 17) ^ x0;
    x0 += x1; x1 = __funnelshift_l(x1, x1, 29) ^ x0;
    x0 += x1; x1 = __funnelshift_l(x1, x1, 16) ^ x0;
    x0 += x1; x1 = __funnelshift_l(x1, x1, 24) ^ x0;
    // inj2 (x0+=k2, x1+=2) merged into round 9's x0-add
    x1 += 2u;
    x0 = x0 + 0x1BD11BF0u + x1;             // IADD3(x0, k2, x1)
    x1 = __funnelshift_l(x1, x1, 13) ^ x0;
    x0 += x1; x1 = __funnelshift_l(x1, x1, 15) ^ x0;
    x0 += x1; x1 = __funnelshift_l(x1, x1, 26) ^ x0;
    x0 += x1; x1 = __funnelshift_l(x1, x1,  6) ^ x0;
    // inj3 (x0+=0, x1+=42+3)
    x1 += 45u;
    x0 = x0 + x1;
    x1 = __funnelshift_l(x1, x1, 17) ^ x0;
    x0 += x1; x1 = __funnelshift_l(x1, x1, 29) ^ x0;
    x0 += x1; x1 = __funnelshift_l(x1, x1, 16) ^ x0;
    x0 += x1; x1 = __funnelshift_l(x1, x1, 24) ^ x0;
    // inj4 (x0+=42, x1+=k2+4) merged into round 17's x0-add
    x1 += 0x1BD11BF4u;                      // k2 + 4
    x0 = x0 + 42u + x1;
    x1 = __funnelshift_l(x1, x1, 13) ^ x0;
    x0 += x1; x1 = __funnelshift_l(x1, x1, 15) ^ x0;
    x0 += x1; x1 = __funnelshift_l(x1, x1, 26) ^ x0;
    x0 += x1; x1 = __funnelshift_l(x1, x1,  6) ^ x0;
    // final injection (x0+=k2, x1+=5), then lane XOR
    return (x0 + 0x1BD11BF0u) ^ (x1 + 5u);
}

// bits -> u in [LO, 1), LO = nextafter(-1,0); bit-exact vs reference.
// funnelshift_r(y, 0x7F, 9) = (y>>9) | (0x7F<<23) = (y>>9) | 0x3F800000.
__device__ __forceinline__ float bits_to_u(uint32_t y) {
    float f = __uint_as_float(__funnelshift_r(y, 0x7Fu, 9)) - 1.0f;
    return fmaf(f, 2.0f, -0.99999994f);
}

// Rare tail (t = w-2.5 >= 2.5, i.e. |u| > 0.99663): full Giles tail poly,
// 0.1*sqrt(2) folded into coefficients.
__device__ __forceinline__ float noise_tail_f(float t, float u) {
    float s = sqrtf(t + 2.5f) - 3.0f;
    float p =       -2.83145467e-05f;
    p = fmaf(p, s,   1.42766481e-05f);
    p = fmaf(p, s,   1.90824894e-04f);
    p = fmaf(p, s,  -5.19499916e-04f);
    p = fmaf(p, s,   8.11690563e-04f);
    p = fmaf(p, s,  -1.07798485e-03f);
    p = fmaf(p, s,   1.33486521e-03f);
    p = fmaf(p, s,   1.41657794e-01f);
    p = fmaf(p, s,   4.00644237e-01f);
    return p * u;
}

__global__ void __launch_bounds__(256)
noise_vec_kernel(const float4* __restrict__ in, float4* __restrict__ out,
                 int n4) {
    int tid = blockIdx.x * blockDim.x + threadIdx.x;
    if (tid >= n4) return;

    float4 a = in[tid];
    uint32_t c42 = 4u * (uint32_t)tid + 42u;   // ctr + key-injection 0

    float u[4], t[4], nz[4];
#pragma unroll
    for (int j = 0; j < 4; j++) {
        uint32_t y = tf_bits(c42 + (uint32_t)j);
        float uu = bits_to_u(y);
        float g = fmaf(-uu, uu, 1.0f);                // 1 - u^2, in (0, 1]
        float lg;
        asm("lg2.approx.f32 %0, %1;" : "=f"(lg) : "f"(g));
        float tt = fmaf(lg, -0.693147181f, -2.5f);    // w - 2.5
        // Central Giles poly deg 4, 0.1*sqrt(2) folded in.
        float p =        3.09122925e-05f;
        p = fmaf(p, tt, -1.77302644e-04f);
        p = fmaf(p, tt, -5.90813690e-04f);
        p = fmaf(p, tt,  3.48802861e-02f);
        p = fmaf(p, tt,  2.12331951e-01f);
        u[j] = uu; t[j] = tt; nz[j] = p * uu;
    }

    // One branch per thread for the rare tail (|u| > 0.99663).
    float mx = fmaxf(fmaxf(t[0], t[1]), fmaxf(t[2], t[3]));
    if (mx >= 2.5f) {
#pragma unroll
        for (int j = 0; j < 4; j++)
            if (t[j] >= 2.5f) nz[j] = noise_tail_f(t[j], u[j]);
    }

    float4 r;
    r.x = a.x + nz[0];
    r.y = a.y + nz[1];
    r.z = a.z + nz[2];
    r.w = a.w + nz[3];
    out[tid] = r;
}

// Scalar fallback for n % 4 != 0 (not hit for this shape).
__global__ void noise_scalar_kernel(const float* __restrict__ in,
                                    float* __restrict__ out,
                                    unsigned int start, unsigned int n) {
    unsigned int i = start + blockIdx.x * blockDim.x + threadIdx.x;
    if (i >= n) return;
    uint32_t y = tf_bits(i + 42u);
    float u = bits_to_u(y);
    float g = fmaf(-u, u, 1.0f);
    float lg;
    asm("lg2.approx.f32 %0, %1;" : "=f"(lg) : "f"(g));
    float t = fmaf(lg, -0.693147181f, -2.5f);
    float p =        3.09122925e-05f;
    p = fmaf(p, t,  -1.77302644e-04f);
    p = fmaf(p, t,  -5.90813690e-04f);
    p = fmaf(p, t,   3.48802861e-02f);
    p = fmaf(p, t,   2.12331951e-01f);
    float nz = (t < 2.5f) ? p * u : noise_tail_f(t, u);
    out[i] = in[i] + nz;
}

extern "C" void kernel_launch(void* const* d_in, const int* in_sizes, int n_in,
                              void* d_out, int out_size) {
    const float* in = (const float*)d_in[0];
    float* out = (float*)d_out;

    unsigned int n = (unsigned int)in_sizes[0];  // 50331648
    int n4 = (int)(n / 4u);                      // 12582912

    if (n4 > 0) {
        int threads = 256;
        int blocks = (n4 + threads - 1) / threads;  // 49152
        noise_vec_kernel<<<blocks, threads>>>((const float4*)in, (float4*)out,
                                              n4);
    }
    unsigned int done = (unsigned int)n4 * 4u;
    if (done < n) {
        unsigned int rem = n - done;
        noise_scalar_kernel<<<(rem + 255) / 256, 256>>>(in, out, done, n);
    }
}